// round 10
// baseline (speedup 1.0000x reference)
#include <cuda_runtime.h>
#include <math.h>

// Problem constants
#define B_   2
#define T_   2048
#define H_   16
#define HD_  64
#define D_   1024          // H_*HD_
#define ND3  3072          // 3*D_
#define M_   4096          // B_*T_

typedef unsigned long long u64;

// Packed fp32x2 ops (Blackwell): ptxas never emits FFMA2 from C++; PTX only.
#define FMA_F32X2(d, a, b, c) \
    asm("fma.rn.f32x2 %0, %1, %2, %3;" : "=l"(d) : "l"(a), "l"(b), "l"(c))
#define MUL_F32X2_(d, a, b) \
    asm("mul.rn.f32x2 %0, %1, %2;" : "=l"(d) : "l"(a), "l"(b))
#define ADD_F32X2_(d, a, b) \
    asm("add.rn.f32x2 %0, %1, %2;" : "=l"(d) : "l"(a), "l"(b))
#define PACK_F32X2(out, lo, hi) \
    asm("mov.b64 %0, {%1, %2};" : "=l"(out) : "r"(__float_as_uint(lo)), "r"(__float_as_uint(hi)))
#define UNPACK_F32X2(lo, hi, in) \
    do { unsigned _ulo, _uhi; \
         asm("mov.b64 {%0, %1}, %2;" : "=r"(_ulo), "=r"(_uhi) : "l"(in)); \
         lo = __uint_as_float(_ulo); hi = __uint_as_float(_uhi); } while (0)

// -------------------- scratch (device globals, no allocation) ---------------
__device__ float g_qkv[(size_t)M_ * ND3];          // [M, 3D]  (b,t major)
__device__ float g_q[(size_t)B_ * H_ * T_ * HD_];  // [B,H,T,hd] (rope'd)
__device__ float g_k[(size_t)B_ * H_ * T_ * HD_];  // [B,H,T,hd] (rope'd)
__device__ float g_v[(size_t)B_ * H_ * T_ * HD_];  // [B,H,T,hd]
__device__ float g_ctx[(size_t)M_ * D_];           // [B,T,D]

// -------------------- GEMM: C = A(MxK) @ B(KxN) + bias ----------------------
// BM=BN=128, BK=8, 8x8 per thread (packed f32x2 accumulators), 256 threads,
// double-buffered smem.
__global__ __launch_bounds__(256) void sgemm_bias_kernel(
    const float* __restrict__ A, const float* __restrict__ Bm,
    const float* __restrict__ bias, float* __restrict__ C,
    int M, int N, int K)
{
    __shared__ __align__(16) float As[2][8][128];
    __shared__ __align__(16) float Bs[2][8][128];

    const int tid = threadIdx.x;
    const int m0 = blockIdx.y * 128;
    const int n0 = blockIdx.x * 128;

    const int arow = tid >> 1;            // 0..127
    const int acol = (tid & 1) * 4;       // 0 or 4
    const int brow = tid >> 5;            // 0..7
    const int bcol = (tid & 31) * 4;      // 0..124

    const float* Aptr = A + (size_t)(m0 + arow) * K + acol;
    const float* Bptr = Bm + (size_t)brow * N + n0 + bcol;

    const int ty = tid >> 4;              // 0..15
    const int tx = tid & 15;              // 0..15

    // packed accumulators: accp[i][j] = cols (2j, 2j+1) of row i
    u64 accp[8][4];
#pragma unroll
    for (int i = 0; i < 8; i++)
#pragma unroll
        for (int j = 0; j < 4; j++) accp[i][j] = 0ull;

    // preload tile 0 into buffer 0
    {
        float4 a4 = *(const float4*)(Aptr);
        float4 b4 = *(const float4*)(Bptr);
        As[0][acol + 0][arow] = a4.x;
        As[0][acol + 1][arow] = a4.y;
        As[0][acol + 2][arow] = a4.z;
        As[0][acol + 3][arow] = a4.w;
        *(float4*)&Bs[0][brow][bcol] = b4;
    }
    __syncthreads();

    int buf = 0;
    for (int k0 = 0; k0 < K; k0 += 8) {
        float4 a_next, b_next;
        const bool more = (k0 + 8) < K;
        if (more) {
            a_next = *(const float4*)(Aptr + k0 + 8);
            b_next = *(const float4*)(Bptr + (size_t)(k0 + 8) * N);
        }

#pragma unroll
        for (int k = 0; k < 8; k++) {
            float4 ra0 = *(const float4*)&As[buf][k][ty * 8];
            float4 ra1 = *(const float4*)&As[buf][k][ty * 8 + 4];
            // two consecutive floats in memory == packed f32x2 operand
            ulonglong2 rbA = *(const ulonglong2*)&Bs[buf][k][tx * 8];
            ulonglong2 rbB = *(const ulonglong2*)&Bs[buf][k][tx * 8 + 4];
            const u64 rb[4] = {rbA.x, rbA.y, rbB.x, rbB.y};
            const float ra[8] = {ra0.x, ra0.y, ra0.z, ra0.w,
                                 ra1.x, ra1.y, ra1.z, ra1.w};
#pragma unroll
            for (int i = 0; i < 8; i++) {
                u64 ap;
                PACK_F32X2(ap, ra[i], ra[i]);
#pragma unroll
                for (int j = 0; j < 4; j++)
                    FMA_F32X2(accp[i][j], ap, rb[j], accp[i][j]);
            }
        }

        if (more) {
            const int nb = buf ^ 1;
            As[nb][acol + 0][arow] = a_next.x;
            As[nb][acol + 1][arow] = a_next.y;
            As[nb][acol + 2][arow] = a_next.z;
            As[nb][acol + 3][arow] = a_next.w;
            *(float4*)&Bs[nb][brow][bcol] = b_next;
            __syncthreads();
            buf = nb;
        }
    }

    // epilogue with bias (packed adds, 16B stores)
    const ulonglong2 bp0 = *(const ulonglong2*)(bias + n0 + tx * 8);
    const ulonglong2 bp1 = *(const ulonglong2*)(bias + n0 + tx * 8 + 4);
    const u64 bb[4] = {bp0.x, bp0.y, bp1.x, bp1.y};
#pragma unroll
    for (int i = 0; i < 8; i++) {
        const int row = m0 + ty * 8 + i;
        float* crow = C + (size_t)row * N + n0 + tx * 8;
        u64 o0, o1, o2, o3;
        ADD_F32X2_(o0, accp[i][0], bb[0]);
        ADD_F32X2_(o1, accp[i][1], bb[1]);
        ADD_F32X2_(o2, accp[i][2], bb[2]);
        ADD_F32X2_(o3, accp[i][3], bb[3]);
        ulonglong2 s0; s0.x = o0; s0.y = o1;
        ulonglong2 s1; s1.x = o2; s1.y = o3;
        *(ulonglong2*)(crow) = s0;
        *(ulonglong2*)(crow + 4) = s1;
    }
}

// -------------------- RoPE + split + cache write -----------------------------
__global__ __launch_bounds__(256) void rope_split_kernel(
    const int* __restrict__ offp, float* __restrict__ cache)
{
    const int p = blockIdx.x * blockDim.x + threadIdx.x;
    if (p >= B_ * T_ * H_ * 32) return;
    const int j = p & 31;
    const int h = (p >> 5) & (H_ - 1);
    const int t = (p >> 9) & (T_ - 1);
    const int b = p >> 20;

    const float* row = g_qkv + (size_t)(b * T_ + t) * ND3 + h * HD_ + 2 * j;
    const float qe = __ldg(row + 0),      qo = __ldg(row + 1);
    const float ke = __ldg(row + D_),     ko = __ldg(row + D_ + 1);
    const float ve = __ldg(row + 2 * D_), vo = __ldg(row + 2 * D_ + 1);

    const float tt = (float)(t + __ldg(offp));
    // inv_freq = 10000^(-2j/64) = 2^(-j * (2/64) * log2(10000))
    const float fr = exp2f(-0.41524101186f * (float)j);
    float s, c;
    sincosf(tt * fr, &s, &c);

    const size_t qidx = (((size_t)(b * H_ + h)) * T_ + t) * HD_ + 2 * j;
    g_q[qidx]     = qe * c - qo * s;
    g_q[qidx + 1] = qe * s + qo * c;
    const float kre = ke * c - ko * s;
    const float kro = ke * s + ko * c;
    g_k[qidx]     = kre;
    g_k[qidx + 1] = kro;
    g_v[qidx]     = ve;
    g_v[qidx + 1] = vo;

    // cache layout: (B, 2, T, H, hd)
    const size_t ck = (((size_t)(b * 2 + 0) * T_ + t) * H_ + h) * HD_ + 2 * j;
    const size_t cv = (((size_t)(b * 2 + 1) * T_ + t) * H_ + h) * HD_ + 2 * j;
    cache[ck]     = kre;
    cache[ck + 1] = kro;
    cache[cv]     = ve;
    cache[cv + 1] = vo;
}

// -------------------- flash attention (fp32, packed f32x2 matmuls) ----------
// BQ=128, BKV=64, 256 threads; thread (tr,tc) owns 8 q-rows x 4 cols.
// smem: Qs[d][r] (64x132), Ks[d][c] (64x68), Vs[c][d] (64x68), Ss[c][r] (64x132)
#define QS_STRIDE 132
#define KS_STRIDE 68
#define ATT_SMEM_FLOATS (64 * QS_STRIDE + 64 * KS_STRIDE + 64 * KS_STRIDE + 64 * QS_STRIDE)
#define ATT_SMEM_BYTES (ATT_SMEM_FLOATS * 4)

__global__ __launch_bounds__(256, 2) void attn_kernel()
{
    extern __shared__ __align__(16) float sm[];
    float* Qs = sm;                          // [64][132] (d, r)
    float* Ks = Qs + 64 * QS_STRIDE;         // [64][68]  (d, c)
    float* Vs = Ks + 64 * KS_STRIDE;         // [64][68]  (c, d)
    float* Ss = Vs + 64 * KS_STRIDE;         // [64][132] (c, r)

    const int tid = threadIdx.x;
    const int qt = blockIdx.x;               // 0..15
    const int bh = blockIdx.y;               // 0..31
    const int b = bh >> 4, h = bh & 15;

    const float* Qp = g_q + ((size_t)bh * T_ + qt * 128) * HD_;
    const float* Kp = g_k + (size_t)bh * T_ * HD_;
    const float* Vp = g_v + (size_t)bh * T_ * HD_;

    const int tr = tid >> 4;                 // 0..15
    const int tc = tid & 15;                 // 0..15
    const int r0 = tr * 8;
    const int c0 = tc * 4;

    // load Q tile transposed: Qs[d][r]
#pragma unroll
    for (int i = tid; i < 128 * 16; i += 256) {
        const int r = i >> 4;
        const int d4 = (i & 15) << 2;
        float4 v = *(const float4*)(Qp + (size_t)r * HD_ + d4);
        Qs[(d4 + 0) * QS_STRIDE + r] = v.x;
        Qs[(d4 + 1) * QS_STRIDE + r] = v.y;
        Qs[(d4 + 2) * QS_STRIDE + r] = v.z;
        Qs[(d4 + 3) * QS_STRIDE + r] = v.w;
    }

    float m_i[8], l_i[8];
    u64 accOp[8][2];                         // packed O pairs (cols 2j,2j+1)
#pragma unroll
    for (int i = 0; i < 8; i++) {
        m_i[i] = -1e30f;
        l_i[i] = 0.f;
        accOp[i][0] = 0ull;
        accOp[i][1] = 0ull;
    }

    const int ntiles = 2 * qt + 2;
    for (int kt = 0; kt < ntiles; kt++) {
        __syncthreads();
        // load K tile transposed + V tile natural
#pragma unroll
        for (int i = tid; i < 64 * 16; i += 256) {
            const int c = i >> 4;
            const int d4 = (i & 15) << 2;
            float4 kv = *(const float4*)(Kp + (size_t)(kt * 64 + c) * HD_ + d4);
            Ks[(d4 + 0) * KS_STRIDE + c] = kv.x;
            Ks[(d4 + 1) * KS_STRIDE + c] = kv.y;
            Ks[(d4 + 2) * KS_STRIDE + c] = kv.z;
            Ks[(d4 + 3) * KS_STRIDE + c] = kv.w;
            float4 vv = *(const float4*)(Vp + (size_t)(kt * 64 + c) * HD_ + d4);
            *(float4*)&Vs[c * KS_STRIDE + d4] = vv;
        }
        __syncthreads();

        // S = Q @ K^T (packed along the 4 s-cols -> 2 pairs)
        u64 accSp[8][2];
#pragma unroll
        for (int i = 0; i < 8; i++) { accSp[i][0] = 0ull; accSp[i][1] = 0ull; }

#pragma unroll 4
        for (int d = 0; d < 64; d++) {
            float4 q0 = *(const float4*)&Qs[d * QS_STRIDE + r0];
            float4 q1 = *(const float4*)&Qs[d * QS_STRIDE + r0 + 4];
            ulonglong2 kp = *(const ulonglong2*)&Ks[d * KS_STRIDE + c0];
            const float qa[8] = {q0.x, q0.y, q0.z, q0.w, q1.x, q1.y, q1.z, q1.w};
#pragma unroll
            for (int i = 0; i < 8; i++) {
                u64 qp;
                PACK_F32X2(qp, qa[i], qa[i]);
                FMA_F32X2(accSp[i][0], qp, kp.x, accSp[i][0]);
                FMA_F32X2(accSp[i][1], qp, kp.y, accSp[i][1]);
            }
        }

        // unpack, scale + causal mask
        float accS[8][4];
        const int rowbase = qt * 128 + r0;
        const int colbase = kt * 64 + c0;
        const bool diag = (kt >= 2 * qt);
#pragma unroll
        for (int i = 0; i < 8; i++) {
            UNPACK_F32X2(accS[i][0], accS[i][1], accSp[i][0]);
            UNPACK_F32X2(accS[i][2], accS[i][3], accSp[i][1]);
#pragma unroll
            for (int j = 0; j < 4; j++) {
                float sv = accS[i][j] * 0.125f;  // 1/sqrt(64)
                if (diag && (colbase + j > rowbase + i)) sv = -1e30f;
                accS[i][j] = sv;
            }
        }

        // online softmax (row state replicated across the 16 tc-lanes)
#pragma unroll
        for (int i = 0; i < 8; i++) {
            float tmax = fmaxf(fmaxf(accS[i][0], accS[i][1]),
                               fmaxf(accS[i][2], accS[i][3]));
#pragma unroll
            for (int s = 1; s < 16; s <<= 1)
                tmax = fmaxf(tmax, __shfl_xor_sync(0xffffffffu, tmax, s));
            const float mnew = fmaxf(m_i[i], tmax);
            const float corr = __expf(m_i[i] - mnew);
            float rs = 0.f;
#pragma unroll
            for (int j = 0; j < 4; j++) {
                const float pij = __expf(accS[i][j] - mnew);
                accS[i][j] = pij;
                rs += pij;
            }
#pragma unroll
            for (int s = 1; s < 16; s <<= 1)
                rs += __shfl_xor_sync(0xffffffffu, rs, s);
            l_i[i] = l_i[i] * corr + rs;
            m_i[i] = mnew;
            u64 corrp;
            PACK_F32X2(corrp, corr, corr);
            MUL_F32X2_(accOp[i][0], accOp[i][0], corrp);
            MUL_F32X2_(accOp[i][1], accOp[i][1], corrp);
        }

        // write P transposed: Ss[c][r]
#pragma unroll
        for (int i = 0; i < 8; i++)
#pragma unroll
            for (int j = 0; j < 4; j++)
                Ss[(c0 + j) * QS_STRIDE + (r0 + i)] = accS[i][j];
        __syncthreads();

        // O += P @ V (packed along the 4 head-dims -> 2 pairs)
#pragma unroll 4
        for (int c = 0; c < 64; c++) {
            float4 p0 = *(const float4*)&Ss[c * QS_STRIDE + r0];
            float4 p1 = *(const float4*)&Ss[c * QS_STRIDE + r0 + 4];
            ulonglong2 vp = *(const ulonglong2*)&Vs[c * KS_STRIDE + c0];
            const float pa[8] = {p0.x, p0.y, p0.z, p0.w, p1.x, p1.y, p1.z, p1.w};
#pragma unroll
            for (int i = 0; i < 8; i++) {
                u64 pp;
                PACK_F32X2(pp, pa[i], pa[i]);
                FMA_F32X2(accOp[i][0], pp, vp.x, accOp[i][0]);
                FMA_F32X2(accOp[i][1], pp, vp.y, accOp[i][1]);
            }
        }
    }

    // epilogue: ctx[b][t][h][d] = O / l
#pragma unroll
    for (int i = 0; i < 8; i++) {
        const float inv = 1.0f / l_i[i];
        const int trow = qt * 128 + r0 + i;
        float o0, o1, o2, o3;
        UNPACK_F32X2(o0, o1, accOp[i][0]);
        UNPACK_F32X2(o2, o3, accOp[i][1]);
        float4 o;
        o.x = o0 * inv;
        o.y = o1 * inv;
        o.z = o2 * inv;
        o.w = o3 * inv;
        *(float4*)(g_ctx + ((size_t)(b * T_ + trow)) * D_ + h * HD_ + c0) = o;
    }
}

// -------------------- launch -------------------------------------------------
extern "C" void kernel_launch(void* const* d_in, const int* in_sizes, int n_in,
                              void* d_out, int out_size)
{
    const float* x    = (const float*)d_in[0];
    const float* Wqkv = (const float*)d_in[1];
    const float* bqkv = (const float*)d_in[2];
    const float* Wout = (const float*)d_in[3];
    const float* bout = (const float*)d_in[4];
    const int*   off  = (const int*)d_in[5];

    float* out   = (float*)d_out;                       // [B,T,D]
    float* cache = out + (size_t)M_ * D_;               // [B,2,T,H,hd]

    float* qkv = nullptr;
    float* ctx = nullptr;
    cudaGetSymbolAddress((void**)&qkv, g_qkv);
    cudaGetSymbolAddress((void**)&ctx, g_ctx);

    // 1. QKV = x @ Wqkv + bqkv
    {
        dim3 grid(ND3 / 128, M_ / 128);
        sgemm_bias_kernel<<<grid, 256>>>(x, Wqkv, bqkv, qkv, M_, ND3, D_);
    }
    // 2. RoPE + split + cache
    {
        const int total = B_ * T_ * H_ * 32;
        rope_split_kernel<<<total / 256, 256>>>(off, cache);
    }
    // 3. flash attention -> g_ctx
    {
        cudaFuncSetAttribute(attn_kernel,
                             cudaFuncAttributeMaxDynamicSharedMemorySize,
                             ATT_SMEM_BYTES);
        attn_kernel<<<dim3(T_ / 128, B_ * H_), 256, ATT_SMEM_BYTES>>>();
    }
    // 4. out = ctx @ Wout + bout
    {
        dim3 grid(D_ / 128, M_ / 128);
        sgemm_bias_kernel<<<grid, 256>>>(ctx, Wout, bout, out, M_, D_, D_);
    }
}

// round 12
// speedup vs baseline: 1.1331x; 1.1331x over previous
#include <cuda_runtime.h>
#include <math.h>

// Problem constants
#define B_   2
#define T_   2048
#define H_   16
#define HD_  64
#define D_   1024          // H_*HD_
#define ND3  3072          // 3*D_
#define M_   4096          // B_*T_

typedef unsigned long long u64;

// Packed fp32x2 ops (Blackwell): ptxas never emits FFMA2 from C++; PTX only.
#define FMA_F32X2(d, a, b, c) \
    asm("fma.rn.f32x2 %0, %1, %2, %3;" : "=l"(d) : "l"(a), "l"(b), "l"(c))
#define MUL_F32X2_(d, a, b) \
    asm("mul.rn.f32x2 %0, %1, %2;" : "=l"(d) : "l"(a), "l"(b))
#define ADD_F32X2_(d, a, b) \
    asm("add.rn.f32x2 %0, %1, %2;" : "=l"(d) : "l"(a), "l"(b))
#define PACK_F32X2(out, lo, hi) \
    asm("mov.b64 %0, {%1, %2};" : "=l"(out) : "r"(__float_as_uint(lo)), "r"(__float_as_uint(hi)))
#define UNPACK_F32X2(lo, hi, in) \
    do { unsigned _ulo, _uhi; \
         asm("mov.b64 {%0, %1}, %2;" : "=r"(_ulo), "=r"(_uhi) : "l"(in)); \
         lo = __uint_as_float(_ulo); hi = __uint_as_float(_uhi); } while (0)

// -------------------- scratch (device globals, no allocation) ---------------
__device__ float g_qkv[(size_t)M_ * ND3];          // [M, 3D]  (b,t major)
__device__ float g_q[(size_t)B_ * H_ * T_ * HD_];  // [B,H,T,hd] (rope'd)
__device__ float g_k[(size_t)B_ * H_ * T_ * HD_];  // [B,H,T,hd] (rope'd)
__device__ float g_v[(size_t)B_ * H_ * T_ * HD_];  // [B,H,T,hd]
__device__ float g_ctx[(size_t)M_ * D_];           // [B,T,D]

// -------------------- GEMM: C = A(MxK) @ B(KxN) + bias ----------------------
// (unchanged from the measured baseline: 214us, fma=50%)
__global__ __launch_bounds__(256) void sgemm_bias_kernel(
    const float* __restrict__ A, const float* __restrict__ Bm,
    const float* __restrict__ bias, float* __restrict__ C,
    int M, int N, int K)
{
    __shared__ __align__(16) float As[2][8][128];
    __shared__ __align__(16) float Bs[2][8][128];

    const int tid = threadIdx.x;
    const int m0 = blockIdx.y * 128;
    const int n0 = blockIdx.x * 128;

    const int arow = tid >> 1;            // 0..127
    const int acol = (tid & 1) * 4;       // 0 or 4
    const int brow = tid >> 5;            // 0..7
    const int bcol = (tid & 31) * 4;      // 0..124

    const float* Aptr = A + (size_t)(m0 + arow) * K + acol;
    const float* Bptr = Bm + (size_t)brow * N + n0 + bcol;

    const int ty = tid >> 4;              // 0..15
    const int tx = tid & 15;              // 0..15

    u64 accp[8][4];
#pragma unroll
    for (int i = 0; i < 8; i++)
#pragma unroll
        for (int j = 0; j < 4; j++) accp[i][j] = 0ull;

    {
        float4 a4 = *(const float4*)(Aptr);
        float4 b4 = *(const float4*)(Bptr);
        As[0][acol + 0][arow] = a4.x;
        As[0][acol + 1][arow] = a4.y;
        As[0][acol + 2][arow] = a4.z;
        As[0][acol + 3][arow] = a4.w;
        *(float4*)&Bs[0][brow][bcol] = b4;
    }
    __syncthreads();

    int buf = 0;
    for (int k0 = 0; k0 < K; k0 += 8) {
        float4 a_next, b_next;
        const bool more = (k0 + 8) < K;
        if (more) {
            a_next = *(const float4*)(Aptr + k0 + 8);
            b_next = *(const float4*)(Bptr + (size_t)(k0 + 8) * N);
        }

#pragma unroll
        for (int k = 0; k < 8; k++) {
            float4 ra0 = *(const float4*)&As[buf][k][ty * 8];
            float4 ra1 = *(const float4*)&As[buf][k][ty * 8 + 4];
            ulonglong2 rbA = *(const ulonglong2*)&Bs[buf][k][tx * 8];
            ulonglong2 rbB = *(const ulonglong2*)&Bs[buf][k][tx * 8 + 4];
            const u64 rb[4] = {rbA.x, rbA.y, rbB.x, rbB.y};
            const float ra[8] = {ra0.x, ra0.y, ra0.z, ra0.w,
                                 ra1.x, ra1.y, ra1.z, ra1.w};
#pragma unroll
            for (int i = 0; i < 8; i++) {
                u64 ap;
                PACK_F32X2(ap, ra[i], ra[i]);
#pragma unroll
                for (int j = 0; j < 4; j++)
                    FMA_F32X2(accp[i][j], ap, rb[j], accp[i][j]);
            }
        }

        if (more) {
            const int nb = buf ^ 1;
            As[nb][acol + 0][arow] = a_next.x;
            As[nb][acol + 1][arow] = a_next.y;
            As[nb][acol + 2][arow] = a_next.z;
            As[nb][acol + 3][arow] = a_next.w;
            *(float4*)&Bs[nb][brow][bcol] = b_next;
            __syncthreads();
            buf = nb;
        }
    }

    const ulonglong2 bp0 = *(const ulonglong2*)(bias + n0 + tx * 8);
    const ulonglong2 bp1 = *(const ulonglong2*)(bias + n0 + tx * 8 + 4);
    const u64 bb[4] = {bp0.x, bp0.y, bp1.x, bp1.y};
#pragma unroll
    for (int i = 0; i < 8; i++) {
        const int row = m0 + ty * 8 + i;
        float* crow = C + (size_t)row * N + n0 + tx * 8;
        u64 o0, o1, o2, o3;
        ADD_F32X2_(o0, accp[i][0], bb[0]);
        ADD_F32X2_(o1, accp[i][1], bb[1]);
        ADD_F32X2_(o2, accp[i][2], bb[2]);
        ADD_F32X2_(o3, accp[i][3], bb[3]);
        ulonglong2 s0; s0.x = o0; s0.y = o1;
        ulonglong2 s1; s1.x = o2; s1.y = o3;
        *(ulonglong2*)(crow) = s0;
        *(ulonglong2*)(crow + 4) = s1;
    }
}

// -------------------- RoPE + split + cache write (unchanged) -----------------
__global__ __launch_bounds__(256) void rope_split_kernel(
    const int* __restrict__ offp, float* __restrict__ cache)
{
    const int p = blockIdx.x * blockDim.x + threadIdx.x;
    if (p >= B_ * T_ * H_ * 32) return;
    const int j = p & 31;
    const int h = (p >> 5) & (H_ - 1);
    const int t = (p >> 9) & (T_ - 1);
    const int b = p >> 20;

    const float* row = g_qkv + (size_t)(b * T_ + t) * ND3 + h * HD_ + 2 * j;
    const float qe = __ldg(row + 0),      qo = __ldg(row + 1);
    const float ke = __ldg(row + D_),     ko = __ldg(row + D_ + 1);
    const float ve = __ldg(row + 2 * D_), vo = __ldg(row + 2 * D_ + 1);

    const float tt = (float)(t + __ldg(offp));
    const float fr = exp2f(-0.41524101186f * (float)j);
    float s, c;
    sincosf(tt * fr, &s, &c);

    const size_t qidx = (((size_t)(b * H_ + h)) * T_ + t) * HD_ + 2 * j;
    g_q[qidx]     = qe * c - qo * s;
    g_q[qidx + 1] = qe * s + qo * c;
    const float kre = ke * c - ko * s;
    const float kro = ke * s + ko * c;
    g_k[qidx]     = kre;
    g_k[qidx + 1] = kro;
    g_v[qidx]     = ve;
    g_v[qidx + 1] = vo;

    const size_t ck = (((size_t)(b * 2 + 0) * T_ + t) * H_ + h) * HD_ + 2 * j;
    const size_t cv = (((size_t)(b * 2 + 1) * T_ + t) * H_ + h) * HD_ + 2 * j;
    cache[ck]     = kre;
    cache[ck + 1] = kro;
    cache[cv]     = ve;
    cache[cv + 1] = vo;
}

// -------------------- flash attention (fp32, fixed-ref softmax) --------------
// Changes vs measured baseline:
//  * fixed softmax reference (m == 0): no per-tile shuffle reductions, no accO
//    rescale; l accumulated as thread-local partial, ONE shuffle reduction at end.
//    (softmax is shift-invariant; fp32 exp overflows only for scores > ~87.)
//  * each block processes q-tiles {x, 15-x}: constant 34 kv-tiles/block;
//    grid (8,32)=256 blocks <= 296 concurrent slots -> one balanced wave.
#define QS_STRIDE 132
#define KS_STRIDE 68
#define ATT_SMEM_FLOATS (64 * QS_STRIDE + 64 * KS_STRIDE + 64 * KS_STRIDE + 64 * QS_STRIDE)
#define ATT_SMEM_BYTES (ATT_SMEM_FLOATS * 4)

__global__ __launch_bounds__(256, 2) void attn_kernel()
{
    extern __shared__ __align__(16) float sm[];
    float* Qs = sm;                          // [64][132] (d, r)
    float* Ks = Qs + 64 * QS_STRIDE;         // [64][68]  (d, c)
    float* Vs = Ks + 64 * KS_STRIDE;         // [64][68]  (c, d)
    float* Ss = Vs + 64 * KS_STRIDE;         // [64][132] (c, r)

    const int tid = threadIdx.x;
    const int bh = blockIdx.y;               // 0..31
    const int b = bh >> 4, h = bh & 15;

    const float* Kp = g_k + (size_t)bh * T_ * HD_;
    const float* Vp = g_v + (size_t)bh * T_ * HD_;

    const int tr = tid >> 4;                 // 0..15
    const int tc = tid & 15;                 // 0..15
    const int r0 = tr * 8;
    const int c0 = tc * 4;

    for (int halfi = 0; halfi < 2; halfi++) {
        const int qt = halfi ? (15 - (int)blockIdx.x) : (int)blockIdx.x;
        const float* Qp = g_q + ((size_t)bh * T_ + qt * 128) * HD_;

        __syncthreads();   // Qs reuse fence between halves

        // load Q tile transposed: Qs[d][r]
        for (int i = tid; i < 128 * 16; i += 256) {
            const int r = i >> 4;
            const int d4 = (i & 15) << 2;
            float4 v = *(const float4*)(Qp + (size_t)r * HD_ + d4);
            Qs[(d4 + 0) * QS_STRIDE + r] = v.x;
            Qs[(d4 + 1) * QS_STRIDE + r] = v.y;
            Qs[(d4 + 2) * QS_STRIDE + r] = v.z;
            Qs[(d4 + 3) * QS_STRIDE + r] = v.w;
        }

        float l_loc[8];                      // thread-local partial row sums
        u64 accOp[8][2];                     // packed O pairs (cols 2j,2j+1)
#pragma unroll
        for (int i = 0; i < 8; i++) {
            l_loc[i] = 0.f;
            accOp[i][0] = 0ull;
            accOp[i][1] = 0ull;
        }

        const int ntiles = 2 * qt + 2;
        for (int kt = 0; kt < ntiles; kt++) {
            __syncthreads();
            // load K tile transposed + V tile natural
            for (int i = tid; i < 64 * 16; i += 256) {
                const int c = i >> 4;
                const int d4 = (i & 15) << 2;
                float4 kv = *(const float4*)(Kp + (size_t)(kt * 64 + c) * HD_ + d4);
                Ks[(d4 + 0) * KS_STRIDE + c] = kv.x;
                Ks[(d4 + 1) * KS_STRIDE + c] = kv.y;
                Ks[(d4 + 2) * KS_STRIDE + c] = kv.z;
                Ks[(d4 + 3) * KS_STRIDE + c] = kv.w;
                float4 vv = *(const float4*)(Vp + (size_t)(kt * 64 + c) * HD_ + d4);
                *(float4*)&Vs[c * KS_STRIDE + d4] = vv;
            }
            __syncthreads();

            // S = Q @ K^T (packed along the 4 s-cols -> 2 pairs)
            u64 accSp[8][2];
#pragma unroll
            for (int i = 0; i < 8; i++) { accSp[i][0] = 0ull; accSp[i][1] = 0ull; }

#pragma unroll 4
            for (int d = 0; d < 64; d++) {
                float4 q0 = *(const float4*)&Qs[d * QS_STRIDE + r0];
                float4 q1 = *(const float4*)&Qs[d * QS_STRIDE + r0 + 4];
                ulonglong2 kp = *(const ulonglong2*)&Ks[d * KS_STRIDE + c0];
                const float qa[8] = {q0.x, q0.y, q0.z, q0.w, q1.x, q1.y, q1.z, q1.w};
#pragma unroll
                for (int i = 0; i < 8; i++) {
                    u64 qp;
                    PACK_F32X2(qp, qa[i], qa[i]);
                    FMA_F32X2(accSp[i][0], qp, kp.x, accSp[i][0]);
                    FMA_F32X2(accSp[i][1], qp, kp.y, accSp[i][1]);
                }
            }

            // unpack, scale + mask, exp (fixed reference 0), local l partials
            const int rowbase = qt * 128 + r0;
            const int colbase = kt * 64 + c0;
            const bool diag = (kt >= 2 * qt);
#pragma unroll
            for (int i = 0; i < 8; i++) {
                float s0, s1, s2, s3;
                UNPACK_F32X2(s0, s1, accSp[i][0]);
                UNPACK_F32X2(s2, s3, accSp[i][1]);
                float sv[4] = {s0, s1, s2, s3};
#pragma unroll
                for (int j = 0; j < 4; j++) {
                    float x = sv[j] * 0.125f;           // 1/sqrt(64)
                    if (diag && (colbase + j > rowbase + i)) x = -1e30f;
                    const float pij = __expf(x);        // masked -> 0
                    sv[j] = pij;
                    l_loc[i] += pij;
                }
                // write P transposed: Ss[c][r]
                Ss[(c0 + 0) * QS_STRIDE + (r0 + i)] = sv[0];
                Ss[(c0 + 1) * QS_STRIDE + (r0 + i)] = sv[1];
                Ss[(c0 + 2) * QS_STRIDE + (r0 + i)] = sv[2];
                Ss[(c0 + 3) * QS_STRIDE + (r0 + i)] = sv[3];
            }
            __syncthreads();

            // O += P @ V (packed along the 4 head-dims -> 2 pairs)
#pragma unroll 4
            for (int c = 0; c < 64; c++) {
                float4 p0 = *(const float4*)&Ss[c * QS_STRIDE + r0];
                float4 p1 = *(const float4*)&Ss[c * QS_STRIDE + r0 + 4];
                ulonglong2 vp = *(const ulonglong2*)&Vs[c * KS_STRIDE + c0];
                const float pa[8] = {p0.x, p0.y, p0.z, p0.w, p1.x, p1.y, p1.z, p1.w};
#pragma unroll
                for (int i = 0; i < 8; i++) {
                    u64 pp;
                    PACK_F32X2(pp, pa[i], pa[i]);
                    FMA_F32X2(accOp[i][0], pp, vp.x, accOp[i][0]);
                    FMA_F32X2(accOp[i][1], pp, vp.y, accOp[i][1]);
                }
            }
        }

        // epilogue: ONE shuffle reduction of l per row, then ctx = O / l
#pragma unroll
        for (int i = 0; i < 8; i++) {
            float l = l_loc[i];
#pragma unroll
            for (int s = 1; s < 16; s <<= 1)
                l += __shfl_xor_sync(0xffffffffu, l, s);
            const float inv = 1.0f / l;
            const int trow = qt * 128 + r0 + i;
            float o0, o1, o2, o3;
            UNPACK_F32X2(o0, o1, accOp[i][0]);
            UNPACK_F32X2(o2, o3, accOp[i][1]);
            float4 o;
            o.x = o0 * inv;
            o.y = o1 * inv;
            o.z = o2 * inv;
            o.w = o3 * inv;
            *(float4*)(g_ctx + ((size_t)(b * T_ + trow)) * D_ + h * HD_ + c0) = o;
        }
    }
}

// -------------------- launch -------------------------------------------------
extern "C" void kernel_launch(void* const* d_in, const int* in_sizes, int n_in,
                              void* d_out, int out_size)
{
    const float* x    = (const float*)d_in[0];
    const float* Wqkv = (const float*)d_in[1];
    const float* bqkv = (const float*)d_in[2];
    const float* Wout = (const float*)d_in[3];
    const float* bout = (const float*)d_in[4];
    const int*   off  = (const int*)d_in[5];

    float* out   = (float*)d_out;                       // [B,T,D]
    float* cache = out + (size_t)M_ * D_;               // [B,2,T,H,hd]

    float* qkv = nullptr;
    float* ctx = nullptr;
    cudaGetSymbolAddress((void**)&qkv, g_qkv);
    cudaGetSymbolAddress((void**)&ctx, g_ctx);

    // 1. QKV = x @ Wqkv + bqkv
    {
        dim3 grid(ND3 / 128, M_ / 128);
        sgemm_bias_kernel<<<grid, 256>>>(x, Wqkv, bqkv, qkv, M_, ND3, D_);
    }
    // 2. RoPE + split + cache
    {
        const int total = B_ * T_ * H_ * 32;
        rope_split_kernel<<<total / 256, 256>>>(off, cache);
    }
    // 3. flash attention -> g_ctx  (each block: q-tiles {x, 15-x}, one wave)
    {
        cudaFuncSetAttribute(attn_kernel,
                             cudaFuncAttributeMaxDynamicSharedMemorySize,
                             ATT_SMEM_BYTES);
        attn_kernel<<<dim3(8, B_ * H_), 256, ATT_SMEM_BYTES>>>();
    }
    // 4. out = ctx @ Wout + bout
    {
        dim3 grid(D_ / 128, M_ / 128);
        sgemm_bias_kernel<<<grid, 256>>>(ctx, Wout, bout, out, M_, D_, D_);
    }
}